// round 1
// baseline (speedup 1.0000x reference)
#include <cuda_runtime.h>

#define NN 25000
#define NE 400000
#define EE (NE + NN)          // 425000 (edges + self loops)
#define SCAN_NB 98            // ceil(NN/256)

// ---------------- scratch (static __device__, no allocs) ----------------
__device__ float g_xall[NN * 4 * 64];   // x_all[N][4][64]
__device__ float g_Q[NN * 64];
__device__ float g_K[NN * 3 * 64];      // K[N][3][64]
__device__ float g_V[NN * 3 * 64];
__device__ float g_dis[NN];
__device__ int   g_deg[NN];
__device__ int   g_off[NN + 1];
__device__ int   g_cur[NN];
__device__ int   g_csr[EE];
__device__ int   g_bsum[SCAN_NB];
__device__ int   g_boff[SCAN_NB];

// ---------------- CSR build ----------------
__global__ void k_init_deg() {
    int i = blockIdx.x * blockDim.x + threadIdx.x;
    if (i < NN) g_deg[i] = 1;   // self loop
}

__global__ void k_hist(const int* __restrict__ ei) {
    int e = blockIdx.x * blockDim.x + threadIdx.x;
    if (e < NE) atomicAdd(&g_deg[ei[NE + e]], 1);   // col = ei[1]
}

__global__ void k_scan_block() {
    __shared__ int sh[256];
    int i = blockIdx.x * 256 + threadIdx.x;
    int v = (i < NN) ? g_deg[i] : 0;
    sh[threadIdx.x] = v;
    __syncthreads();
    for (int o = 1; o < 256; o <<= 1) {
        int t = (threadIdx.x >= o) ? sh[threadIdx.x - o] : 0;
        __syncthreads();
        sh[threadIdx.x] += t;
        __syncthreads();
    }
    if (i < NN) g_off[i] = sh[threadIdx.x] - v;       // exclusive within block
    if (threadIdx.x == 255) g_bsum[blockIdx.x] = sh[255];
}

__global__ void k_scan_top() {
    __shared__ int sh[128];
    int t = threadIdx.x;
    int v = (t < SCAN_NB) ? g_bsum[t] : 0;
    sh[t] = v;
    __syncthreads();
    for (int o = 1; o < 128; o <<= 1) {
        int tmp = (t >= o) ? sh[t - o] : 0;
        __syncthreads();
        sh[t] += tmp;
        __syncthreads();
    }
    if (t < SCAN_NB) g_boff[t] = sh[t] - v;
}

__global__ void k_scan_fix() {
    int i = blockIdx.x * blockDim.x + threadIdx.x;
    if (i < NN) {
        int o = g_off[i] + g_boff[i >> 8];
        g_off[i] = o;
        g_cur[i] = o;
        g_dis[i] = rsqrtf((float)g_deg[i]);
    }
    if (i == 0) g_off[NN] = EE;
}

__global__ void k_scatter(const int* __restrict__ ei) {
    int idx = blockIdx.x * blockDim.x + threadIdx.x;
    if (idx >= EE) return;
    int r, c;
    if (idx < NE) { r = ei[idx]; c = ei[NE + idx]; }
    else          { r = c = idx - NE; }               // self loop
    int p = atomicAdd(&g_cur[c], 1);
    g_csr[p] = r;
}

// ---------------- lin1: h = relu(x @ W1 + b1) -> x_all[:,0,:] ----------------
// warp handles 4 nodes; lane covers outputs {2*lane, 2*lane+1} via float2
__global__ void k_lin1(const float* __restrict__ x, const float* __restrict__ w,
                       const float* __restrict__ b) {
    int gw = (blockIdx.x * blockDim.x + threadIdx.x) >> 5;
    int lane = threadIdx.x & 31;
    int base = gw * 4;                 // NN % 4 == 0
    if (base >= NN) return;
    const float2* W2 = (const float2*)w;   // [256][32] float2
    float2 a0 = {0.f, 0.f}, a1 = {0.f, 0.f}, a2 = {0.f, 0.f}, a3 = {0.f, 0.f};
    for (int k0 = 0; k0 < 256; k0 += 32) {
        float x0 = x[(base + 0) * 256 + k0 + lane];
        float x1 = x[(base + 1) * 256 + k0 + lane];
        float x2 = x[(base + 2) * 256 + k0 + lane];
        float x3 = x[(base + 3) * 256 + k0 + lane];
#pragma unroll
        for (int kk = 0; kk < 32; kk++) {
            float2 wv = W2[(k0 + kk) * 32 + lane];
            float b0 = __shfl_sync(0xffffffffu, x0, kk);
            float b1v = __shfl_sync(0xffffffffu, x1, kk);
            float b2v = __shfl_sync(0xffffffffu, x2, kk);
            float b3v = __shfl_sync(0xffffffffu, x3, kk);
            a0.x += b0 * wv.x;  a0.y += b0 * wv.y;
            a1.x += b1v * wv.x; a1.y += b1v * wv.y;
            a2.x += b2v * wv.x; a2.y += b2v * wv.y;
            a3.x += b3v * wv.x; a3.y += b3v * wv.y;
        }
    }
    float2 bb = ((const float2*)b)[lane];
    float2* o0 = (float2*)&g_xall[((size_t)(base + 0) * 4 + 0) * 64];
    float2* o1 = (float2*)&g_xall[((size_t)(base + 1) * 4 + 0) * 64];
    float2* o2 = (float2*)&g_xall[((size_t)(base + 2) * 4 + 0) * 64];
    float2* o3 = (float2*)&g_xall[((size_t)(base + 3) * 4 + 0) * 64];
    o0[lane] = make_float2(fmaxf(a0.x + bb.x, 0.f), fmaxf(a0.y + bb.y, 0.f));
    o1[lane] = make_float2(fmaxf(a1.x + bb.x, 0.f), fmaxf(a1.y + bb.y, 0.f));
    o2[lane] = make_float2(fmaxf(a2.x + bb.x, 0.f), fmaxf(a2.y + bb.y, 0.f));
    o3[lane] = make_float2(fmaxf(a3.x + bb.x, 0.f), fmaxf(a3.y + bb.y, 0.f));
}

// ---------------- per-layer QKV (grouped linear, per node) ----------------
// one warp per (node, layer): computes K,V rows; if layer == L-1 also Q
template <int L>
__global__ void k_qkv(const float* __restrict__ wq, const float* __restrict__ bq,
                      const float* __restrict__ wk, const float* __restrict__ bk,
                      const float* __restrict__ wv, const float* __restrict__ bv) {
    __shared__ float swq[512], swk[512], swv[512], sbq[64], sbk[64], sbv[64];
    for (int i = threadIdx.x; i < 512; i += blockDim.x) {
        swq[i] = wq[i]; swk[i] = wk[i]; swv[i] = wv[i];
    }
    if (threadIdx.x < 64) {
        sbq[threadIdx.x] = bq[threadIdx.x];
        sbk[threadIdx.x] = bk[threadIdx.x];
        sbv[threadIdx.x] = bv[threadIdx.x];
    }
    __syncthreads();
    int item = (blockIdx.x * blockDim.x + threadIdx.x) >> 5;
    if (item >= NN * L) return;
    int lane = threadIdx.x & 31;
    int n = item / L;
    int layer = item - n * L;

    float x0 = g_xall[((size_t)n * 4 + layer) * 64 + lane];
    float x1 = g_xall[((size_t)n * 4 + layer) * 64 + lane + 32];
    int g0 = lane >> 3;          // group for output o=lane
    int oo = lane & 7;
    float xa[8], xb[8];
#pragma unroll
    for (int i = 0; i < 8; i++) {
        xa[i] = __shfl_sync(0xffffffffu, x0, g0 * 8 + i);  // x[g0*8+i]
        xb[i] = __shfl_sync(0xffffffffu, x1, g0 * 8 + i);  // x[(g0+4)*8+i]
    }
    int wb0 = (g0 * 8) * 8 + oo;
    int wb1 = ((g0 + 4) * 8) * 8 + oo;
    float k0 = sbk[lane], k1 = sbk[lane + 32];
    float v0 = sbv[lane], v1 = sbv[lane + 32];
#pragma unroll
    for (int i = 0; i < 8; i++) {
        k0 += xa[i] * swk[wb0 + i * 8];
        k1 += xb[i] * swk[wb1 + i * 8];
        v0 += xa[i] * swv[wb0 + i * 8];
        v1 += xb[i] * swv[wb1 + i * 8];
    }
    size_t kb = ((size_t)n * 3 + layer) * 64;
    g_K[kb + lane] = k0; g_K[kb + lane + 32] = k1;
    g_V[kb + lane] = v0; g_V[kb + lane + 32] = v1;
    if (layer == L - 1) {
        float q0 = sbq[lane], q1 = sbq[lane + 32];
#pragma unroll
        for (int i = 0; i < 8; i++) {
            q0 += xa[i] * swq[wb0 + i * 8];
            q1 += xb[i] * swq[wb1 + i * 8];
        }
        g_Q[(size_t)n * 64 + lane] = q0;
        g_Q[(size_t)n * 64 + lane + 32] = q1;
    }
}

// ---------------- edge/attention + segment-sum + relu ----------------
// one warp per destination node; lane covers float2 element `lane`
// head = lane/4 (8 heads x 4 float2 = 64 dims); dot reduced over 4 lanes
template <int L>
__global__ void k_edge() {
    int c = (blockIdx.x * blockDim.x + threadIdx.x) >> 5;
    if (c >= NN) return;
    int lane = threadIdx.x & 31;
    float dis_c = g_dis[c];
    float2 qv = ((const float2*)g_Q)[(size_t)c * 32 + lane];
    float2 acc = make_float2(0.f, 0.f);
    int j = g_off[c], end = g_off[c + 1];
    const float sc = 0.35355339059327378f;   // 1/sqrt(8)
    for (; j < end; ++j) {
        int r = g_csr[j];
        float nrm = dis_c * g_dis[r];
        const float2* Kr = ((const float2*)g_K) + (size_t)r * 96;
        const float2* Vr = ((const float2*)g_V) + (size_t)r * 96;
        float2 kv[L], vv[L];
#pragma unroll
        for (int l = 0; l < L; l++) kv[l] = Kr[l * 32 + lane];
#pragma unroll
        for (int l = 0; l < L; l++) vv[l] = Vr[l * 32 + lane];
        float s[L];
#pragma unroll
        for (int l = 0; l < L; l++) {
            float p = qv.x * kv[l].x + qv.y * kv[l].y;
            p += __shfl_xor_sync(0xffffffffu, p, 1);
            p += __shfl_xor_sync(0xffffffffu, p, 2);
            s[l] = p;     // full head dot, replicated across 4-lane group
        }
        float m = s[0];
#pragma unroll
        for (int l = 1; l < L; l++) m = fmaxf(m, s[l]);
        float e[L], sum = 0.f;
#pragma unroll
        for (int l = 0; l < L; l++) { e[l] = __expf((s[l] - m) * sc); sum += e[l]; }
        float2 t = make_float2(0.f, 0.f);
#pragma unroll
        for (int l = 0; l < L; l++) { t.x += e[l] * vv[l].x; t.y += e[l] * vv[l].y; }
        float w = nrm / sum;
        acc.x += w * t.x;
        acc.y += w * t.y;
    }
    float2* xo = (float2*)&g_xall[((size_t)c * 4 + L) * 64];   // write layer L (=l+1)
    xo[lane] = make_float2(fmaxf(acc.x, 0.f), fmaxf(acc.y, 0.f));
}

// ---------------- lin2 + log_softmax ----------------
__global__ void k_lin2(const float* __restrict__ w, const float* __restrict__ b,
                       float* __restrict__ out) {
    __shared__ float sw[2048];   // [64][32]
    __shared__ float sb[32];
    for (int i = threadIdx.x; i < 2048; i += blockDim.x) sw[i] = w[i];
    if (threadIdx.x < 32) sb[threadIdx.x] = b[threadIdx.x];
    __syncthreads();
    int n = (blockIdx.x * blockDim.x + threadIdx.x) >> 5;
    if (n >= NN) return;
    int lane = threadIdx.x & 31;   // lane = class
    float x0 = g_xall[((size_t)n * 4 + 3) * 64 + lane];
    float x1 = g_xall[((size_t)n * 4 + 3) * 64 + lane + 32];
    float acc = sb[lane];
#pragma unroll
    for (int k = 0; k < 32; k++) acc += __shfl_sync(0xffffffffu, x0, k) * sw[k * 32 + lane];
#pragma unroll
    for (int k = 0; k < 32; k++) acc += __shfl_sync(0xffffffffu, x1, k) * sw[(k + 32) * 32 + lane];
    float m = acc;
#pragma unroll
    for (int o = 16; o; o >>= 1) m = fmaxf(m, __shfl_xor_sync(0xffffffffu, m, o));
    float e = __expf(acc - m);
    float sum = e;
#pragma unroll
    for (int o = 16; o; o >>= 1) sum += __shfl_xor_sync(0xffffffffu, sum, o);
    out[(size_t)n * 32 + lane] = acc - m - logf(sum);
}

// ---------------- launch ----------------
extern "C" void kernel_launch(void* const* d_in, const int* in_sizes, int n_in,
                              void* d_out, int out_size) {
    const float* x  = (const float*)d_in[0];
    const int*   ei = (const int*)d_in[1];
    const float* w1 = (const float*)d_in[2];
    const float* b1 = (const float*)d_in[3];
    const float* wq = (const float*)d_in[4];
    const float* bq = (const float*)d_in[5];
    const float* wk = (const float*)d_in[6];
    const float* bk = (const float*)d_in[7];
    const float* wv = (const float*)d_in[8];
    const float* bv = (const float*)d_in[9];
    const float* w2 = (const float*)d_in[10];
    const float* b2 = (const float*)d_in[11];
    float* out = (float*)d_out;

    // CSR + norm
    k_init_deg<<<(NN + 255) / 256, 256>>>();
    k_hist<<<(NE + 255) / 256, 256>>>(ei);
    k_scan_block<<<SCAN_NB, 256>>>();
    k_scan_top<<<1, 128>>>();
    k_scan_fix<<<SCAN_NB, 256>>>();
    k_scatter<<<(EE + 255) / 256, 256>>>(ei);

    // encoder
    k_lin1<<<((NN / 4) * 32 + 255) / 256, 256>>>(x, w1, b1);

    // layer 0 (L=1)
    k_qkv<1><<<(NN * 1 * 32 + 255) / 256, 256>>>(wq, bq, wk, bk, wv, bv);
    k_edge<1><<<(NN * 32 + 255) / 256, 256>>>();
    // layer 1 (L=2)
    k_qkv<2><<<(NN * 2 * 32 + 255) / 256, 256>>>(wq + 512, bq + 64, wk + 512, bk + 64, wv + 512, bv + 64);
    k_edge<2><<<(NN * 32 + 255) / 256, 256>>>();
    // layer 2 (L=3)
    k_qkv<3><<<(NN * 3 * 32 + 255) / 256, 256>>>(wq + 1024, bq + 128, wk + 1024, bk + 128, wv + 1024, bv + 128);
    k_edge<3><<<(NN * 32 + 255) / 256, 256>>>();

    // classifier
    k_lin2<<<(NN * 32 + 255) / 256, 256>>>(w2, b2, out);
}

// round 2
// speedup vs baseline: 1.1541x; 1.1541x over previous
#include <cuda_runtime.h>

#define NN 25000
#define NE 400000
#define EE (NE + NN)          // 425000 (edges + self loops)
#define SCAN_NB 98            // ceil(NN/256)
#define SC 0.35355339059327378f   // 1/sqrt(8)

// ---------------- scratch (static __device__, no allocs) ----------------
__device__ float  g_xall[NN * 4 * 64];   // x_all[N][4][64]
__device__ float  g_Q[NN * 64];          // float2 per lane: dims {2l,2l+1}, pre-scaled by SC
__device__ float4 g_KV[NN * 96];         // [N][3 layers][32 lanes] {Kx,Ky,Vx*dis,Vy*dis}
__device__ float  g_dis[NN];
__device__ int    g_deg[NN];
__device__ int    g_off[NN + 1];
__device__ int    g_cur[NN];
__device__ int    g_csr[EE];
__device__ int    g_bsum[SCAN_NB];
__device__ int    g_boff[SCAN_NB];

// ---------------- CSR build ----------------
__global__ void k_init_deg() {
    int i = blockIdx.x * blockDim.x + threadIdx.x;
    if (i < NN) g_deg[i] = 1;   // self loop
}

__global__ void k_hist(const int* __restrict__ ei) {
    int e = blockIdx.x * blockDim.x + threadIdx.x;
    if (e < NE) atomicAdd(&g_deg[ei[NE + e]], 1);   // col = ei[1]
}

__global__ void k_scan_block() {
    __shared__ int sh[256];
    int i = blockIdx.x * 256 + threadIdx.x;
    int v = (i < NN) ? g_deg[i] : 0;
    sh[threadIdx.x] = v;
    __syncthreads();
    for (int o = 1; o < 256; o <<= 1) {
        int t = (threadIdx.x >= o) ? sh[threadIdx.x - o] : 0;
        __syncthreads();
        sh[threadIdx.x] += t;
        __syncthreads();
    }
    if (i < NN) g_off[i] = sh[threadIdx.x] - v;       // exclusive within block
    if (threadIdx.x == 255) g_bsum[blockIdx.x] = sh[255];
}

__global__ void k_scan_top() {
    __shared__ int sh[128];
    int t = threadIdx.x;
    int v = (t < SCAN_NB) ? g_bsum[t] : 0;
    sh[t] = v;
    __syncthreads();
    for (int o = 1; o < 128; o <<= 1) {
        int tmp = (t >= o) ? sh[t - o] : 0;
        __syncthreads();
        sh[t] += tmp;
        __syncthreads();
    }
    if (t < SCAN_NB) g_boff[t] = sh[t] - v;
}

__global__ void k_scan_fix() {
    int i = blockIdx.x * blockDim.x + threadIdx.x;
    if (i < NN) {
        int o = g_off[i] + g_boff[i >> 8];
        g_off[i] = o;
        g_cur[i] = o;
        g_dis[i] = rsqrtf((float)g_deg[i]);
    }
    if (i == 0) g_off[NN] = EE;
}

__global__ void k_scatter(const int* __restrict__ ei) {
    int idx = blockIdx.x * blockDim.x + threadIdx.x;
    if (idx >= EE) return;
    int r, c;
    if (idx < NE) { r = ei[idx]; c = ei[NE + idx]; }
    else          { r = c = idx - NE; }               // self loop
    int p = atomicAdd(&g_cur[c], 1);
    g_csr[p] = r;
}

// ---------------- lin1: h = relu(x @ W1 + b1) -> x_all[:,0,:] ----------------
// warp handles 8 nodes; lane covers outputs {2*lane, 2*lane+1} via float2
__global__ void k_lin1(const float* __restrict__ x, const float* __restrict__ w,
                       const float* __restrict__ b) {
    int gw = (blockIdx.x * blockDim.x + threadIdx.x) >> 5;
    int lane = threadIdx.x & 31;
    int base = gw * 8;                 // NN % 8 == 0
    if (base >= NN) return;
    const float2* W2 = (const float2*)w;   // [256][32] float2
    float2 acc[8];
#pragma unroll
    for (int n = 0; n < 8; n++) acc[n] = make_float2(0.f, 0.f);
    for (int k0 = 0; k0 < 256; k0 += 32) {
        float xr[8];
#pragma unroll
        for (int n = 0; n < 8; n++) xr[n] = x[(base + n) * 256 + k0 + lane];
#pragma unroll
        for (int kk = 0; kk < 32; kk++) {
            float2 wv = W2[(k0 + kk) * 32 + lane];
#pragma unroll
            for (int n = 0; n < 8; n++) {
                float bv = __shfl_sync(0xffffffffu, xr[n], kk);
                acc[n].x += bv * wv.x;
                acc[n].y += bv * wv.y;
            }
        }
    }
    float2 bb = ((const float2*)b)[lane];
#pragma unroll
    for (int n = 0; n < 8; n++) {
        float2* o = (float2*)&g_xall[((size_t)(base + n) * 4 + 0) * 64];
        o[lane] = make_float2(fmaxf(acc[n].x + bb.x, 0.f), fmaxf(acc[n].y + bb.y, 0.f));
    }
}

// ---------------- per-layer QKV (grouped linear, per node) ----------------
// one warp per (node, layer): lane computes output dims {2*lane, 2*lane+1}
// writes interleaved KV float4 {Kx,Ky,Vx*dis,Vy*dis}; if layer == L-1 also Q*SC
template <int L>
__global__ void k_qkv(const float* __restrict__ wq, const float* __restrict__ bq,
                      const float* __restrict__ wk, const float* __restrict__ bk,
                      const float* __restrict__ wv, const float* __restrict__ bv) {
    __shared__ float swq[512], swk[512], swv[512], sbq[64], sbk[64], sbv[64];
    for (int i = threadIdx.x; i < 512; i += blockDim.x) {
        swq[i] = wq[i]; swk[i] = wk[i]; swv[i] = wv[i];
    }
    if (threadIdx.x < 64) {
        sbq[threadIdx.x] = bq[threadIdx.x];
        sbk[threadIdx.x] = bk[threadIdx.x];
        sbv[threadIdx.x] = bv[threadIdx.x];
    }
    __syncthreads();
    int item = (blockIdx.x * blockDim.x + threadIdx.x) >> 5;
    if (item >= NN * L) return;
    int lane = threadIdx.x & 31;
    int n = item / L;
    int layer = item - n * L;

    const float* xr = &g_xall[((size_t)n * 4 + layer) * 64];
    float x0 = xr[lane], x1 = xr[lane + 32];
    int g0 = lane >> 2;                  // group of output dim 2*lane
    float xa[8];
#pragma unroll
    for (int i = 0; i < 8; i++) {
        int idx = g0 * 8 + i;
        float a = __shfl_sync(0xffffffffu, x0, idx & 31);
        float bsh = __shfl_sync(0xffffffffu, x1, idx & 31);
        xa[i] = (idx < 32) ? a : bsh;
    }
    // float2 weight base: element (g,i,o) at g*64+i*8+o; pair (o even)
    int wbase = g0 * 32 + (lane & 3);
    const float2* wk2 = (const float2*)swk;
    const float2* wv2 = (const float2*)swv;
    float2 kk = ((const float2*)sbk)[lane];
    float2 vv = ((const float2*)sbv)[lane];
#pragma unroll
    for (int i = 0; i < 8; i++) {
        float2 wkv = wk2[wbase + i * 4];
        kk.x += xa[i] * wkv.x;  kk.y += xa[i] * wkv.y;
        float2 wvv = wv2[wbase + i * 4];
        vv.x += xa[i] * wvv.x;  vv.y += xa[i] * wvv.y;
    }
    float dr = g_dis[n];
    g_KV[(size_t)n * 96 + layer * 32 + lane] = make_float4(kk.x, kk.y, vv.x * dr, vv.y * dr);
    if (layer == L - 1) {
        const float2* wq2 = (const float2*)swq;
        float2 qq = ((const float2*)sbq)[lane];
#pragma unroll
        for (int i = 0; i < 8; i++) {
            float2 wqv = wq2[wbase + i * 4];
            qq.x += xa[i] * wqv.x;  qq.y += xa[i] * wqv.y;
        }
        ((float2*)g_Q)[(size_t)n * 32 + lane] = make_float2(qq.x * SC, qq.y * SC);
    }
}

// ---------------- edge/attention + segment-sum + relu ----------------
template <int L>
__device__ __forceinline__ void edge_accum(const float4 (&kv)[L], float2 qv,
                                           float& ax, float& ay) {
    if constexpr (L == 1) {
        ax += kv[0].z;  ay += kv[0].w;   // softmax over 1 element == 1
    } else {
        float s[L];
#pragma unroll
        for (int l = 0; l < L; l++) {
            float p = qv.x * kv[l].x + qv.y * kv[l].y;
            p += __shfl_xor_sync(0xffffffffu, p, 1);
            p += __shfl_xor_sync(0xffffffffu, p, 2);
            s[l] = p;     // head dot (Q pre-scaled by 1/sqrt(dh))
        }
        float m = s[0];
#pragma unroll
        for (int l = 1; l < L; l++) m = fmaxf(m, s[l]);
        float sum = 0.f, tx = 0.f, ty = 0.f;
#pragma unroll
        for (int l = 0; l < L; l++) {
            float e = __expf(s[l] - m);
            sum += e;
            tx += e * kv[l].z;
            ty += e * kv[l].w;
        }
        float w = __fdividef(1.0f, sum);
        ax += w * tx;  ay += w * ty;
    }
}

// one warp per destination node; lane covers dims {2*lane,2*lane+1}
template <int L>
__global__ void k_edge() {
    int c = (blockIdx.x * blockDim.x + threadIdx.x) >> 5;
    if (c >= NN) return;
    int lane = threadIdx.x & 31;
    float2 qv = ((const float2*)g_Q)[(size_t)c * 32 + lane];
    float ax = 0.f, ay = 0.f;
    int j = g_off[c], end = g_off[c + 1];
    const float4* __restrict__ KV = g_KV;
    for (; j + 2 <= end; j += 2) {
        int r0 = g_csr[j], r1 = g_csr[j + 1];
        const float4* p0 = KV + (size_t)r0 * 96 + lane;
        const float4* p1 = KV + (size_t)r1 * 96 + lane;
        float4 kv0[L], kv1[L];
#pragma unroll
        for (int l = 0; l < L; l++) kv0[l] = p0[l * 32];
#pragma unroll
        for (int l = 0; l < L; l++) kv1[l] = p1[l * 32];
        edge_accum<L>(kv0, qv, ax, ay);
        edge_accum<L>(kv1, qv, ax, ay);
    }
    if (j < end) {
        int r0 = g_csr[j];
        const float4* p0 = KV + (size_t)r0 * 96 + lane;
        float4 kv0[L];
#pragma unroll
        for (int l = 0; l < L; l++) kv0[l] = p0[l * 32];
        edge_accum<L>(kv0, qv, ax, ay);
    }
    float dc = g_dis[c];
    float2* xo = (float2*)&g_xall[((size_t)c * 4 + L) * 64];   // write layer L (=l+1)
    xo[lane] = make_float2(fmaxf(ax * dc, 0.f), fmaxf(ay * dc, 0.f));
}

// ---------------- lin2 + log_softmax ----------------
__global__ void k_lin2(const float* __restrict__ w, const float* __restrict__ b,
                       float* __restrict__ out) {
    __shared__ float sw[2048];   // [64][32]
    __shared__ float sb[32];
    for (int i = threadIdx.x; i < 2048; i += blockDim.x) sw[i] = w[i];
    if (threadIdx.x < 32) sb[threadIdx.x] = b[threadIdx.x];
    __syncthreads();
    int n = (blockIdx.x * blockDim.x + threadIdx.x) >> 5;
    if (n >= NN) return;
    int lane = threadIdx.x & 31;   // lane = class
    float x0 = g_xall[((size_t)n * 4 + 3) * 64 + lane];
    float x1 = g_xall[((size_t)n * 4 + 3) * 64 + lane + 32];
    float acc = sb[lane];
#pragma unroll
    for (int k = 0; k < 32; k++) acc += __shfl_sync(0xffffffffu, x0, k) * sw[k * 32 + lane];
#pragma unroll
    for (int k = 0; k < 32; k++) acc += __shfl_sync(0xffffffffu, x1, k) * sw[(k + 32) * 32 + lane];
    float m = acc;
#pragma unroll
    for (int o = 16; o; o >>= 1) m = fmaxf(m, __shfl_xor_sync(0xffffffffu, m, o));
    float e = __expf(acc - m);
    float sum = e;
#pragma unroll
    for (int o = 16; o; o >>= 1) sum += __shfl_xor_sync(0xffffffffu, sum, o);
    out[(size_t)n * 32 + lane] = acc - m - logf(sum);
}

// ---------------- launch ----------------
extern "C" void kernel_launch(void* const* d_in, const int* in_sizes, int n_in,
                              void* d_out, int out_size) {
    const float* x  = (const float*)d_in[0];
    const int*   ei = (const int*)d_in[1];
    const float* w1 = (const float*)d_in[2];
    const float* b1 = (const float*)d_in[3];
    const float* wq = (const float*)d_in[4];
    const float* bq = (const float*)d_in[5];
    const float* wk = (const float*)d_in[6];
    const float* bk = (const float*)d_in[7];
    const float* wv = (const float*)d_in[8];
    const float* bv = (const float*)d_in[9];
    const float* w2 = (const float*)d_in[10];
    const float* b2 = (const float*)d_in[11];
    float* out = (float*)d_out;

    // CSR + norm
    k_init_deg<<<(NN + 255) / 256, 256>>>();
    k_hist<<<(NE + 255) / 256, 256>>>(ei);
    k_scan_block<<<SCAN_NB, 256>>>();
    k_scan_top<<<1, 128>>>();
    k_scan_fix<<<SCAN_NB, 256>>>();
    k_scatter<<<(EE + 255) / 256, 256>>>(ei);

    // encoder
    k_lin1<<<((NN / 8) * 32 + 255) / 256, 256>>>(x, w1, b1);

    // layer 0 (L=1)
    k_qkv<1><<<(NN * 1 * 32 + 255) / 256, 256>>>(wq, bq, wk, bk, wv, bv);
    k_edge<1><<<(NN * 32 + 255) / 256, 256>>>();
    // layer 1 (L=2)
    k_qkv<2><<<(NN * 2 * 32 + 255) / 256, 256>>>(wq + 512, bq + 64, wk + 512, bk + 64, wv + 512, bv + 64);
    k_edge<2><<<(NN * 32 + 255) / 256, 256>>>();
    // layer 2 (L=3)
    k_qkv<3><<<(NN * 3 * 32 + 255) / 256, 256>>>(wq + 1024, bq + 128, wk + 1024, bk + 128, wv + 1024, bv + 128);
    k_edge<3><<<(NN * 32 + 255) / 256, 256>>>();

    // classifier
    k_lin2<<<(NN * 32 + 255) / 256, 256>>>(w2, b2, out);
}

// round 3
// speedup vs baseline: 1.4513x; 1.2575x over previous
#include <cuda_runtime.h>
#include <cuda_fp16.h>

#define NN 25000
#define NE 400000
#define EE (NE + NN)          // 425000 (edges + self loops)
#define SCAN_NB 98            // ceil(NN/256)
#define SC 0.35355339059327378f   // 1/sqrt(8)

// ---------------- scratch (static __device__, no allocs) ----------------
__device__ float    g_xall[NN * 4 * 64];   // x_all[N][4][64] fp32
__device__ float2   g_Q[NN * 32];          // per lane dims {2l,2l+1}, pre-scaled by SC
__device__ unsigned g_V1[NN * 32];         // layer-0 V as half2 {v.x*dis, v.y*dis}
__device__ uint4    g_KVab[NN * 32];       // {K_l0, V_l0, K_l1, V_l1} half2 each
__device__ uint2    g_KVc[NN * 32];        // {K_l2, V_l2} half2 each
__device__ float    g_dis[NN];
__device__ int      g_deg[NN];
__device__ int      g_off[NN + 1];
__device__ int      g_cur[NN];
__device__ int      g_csr[EE];
__device__ int      g_bsum[SCAN_NB];

__device__ __forceinline__ float2 u2f(unsigned u) {
    return __half22float2(*reinterpret_cast<const __half2*>(&u));
}
__device__ __forceinline__ unsigned f2u(float x, float y) {
    __half2 h = __floats2half2_rn(x, y);
    return *reinterpret_cast<unsigned*>(&h);
}

// ---------------- CSR build ----------------
__global__ void k_init_deg() {
    int i = blockIdx.x * blockDim.x + threadIdx.x;
    if (i < NN) g_deg[i] = 1;   // self loop
}

__global__ void k_hist(const int* __restrict__ ei) {
    int e = blockIdx.x * blockDim.x + threadIdx.x;
    if (e < NE) atomicAdd(&g_deg[ei[NE + e]], 1);   // col = ei[1]
}

__global__ void k_scan_block() {
    __shared__ int sh[256];
    int i = blockIdx.x * 256 + threadIdx.x;
    int v = (i < NN) ? g_deg[i] : 0;
    sh[threadIdx.x] = v;
    __syncthreads();
    for (int o = 1; o < 256; o <<= 1) {
        int t = (threadIdx.x >= o) ? sh[threadIdx.x - o] : 0;
        __syncthreads();
        sh[threadIdx.x] += t;
        __syncthreads();
    }
    if (i < NN) g_off[i] = sh[threadIdx.x] - v;       // exclusive within block
    if (threadIdx.x == 255) g_bsum[blockIdx.x] = sh[255];
}

// fused top-scan + fixup
__global__ void k_scan_fix() {
    __shared__ int s_boff;
    int bid = blockIdx.x;
    if (threadIdx.x < 32) {
        int s = 0;
        for (int k = threadIdx.x; k < bid; k += 32) s += g_bsum[k];
#pragma unroll
        for (int o = 16; o; o >>= 1) s += __shfl_xor_sync(0xffffffffu, s, o);
        if (threadIdx.x == 0) s_boff = s;
    }
    __syncthreads();
    int i = bid * 256 + threadIdx.x;
    if (i < NN) {
        int o = g_off[i] + s_boff;
        g_off[i] = o;
        g_cur[i] = o;
        g_dis[i] = rsqrtf((float)g_deg[i]);
    }
    if (i == 0) g_off[NN] = EE;
}

__global__ void k_scatter(const int* __restrict__ ei) {
    int idx = blockIdx.x * blockDim.x + threadIdx.x;
    if (idx >= EE) return;
    int r, c;
    if (idx < NE) { r = ei[idx]; c = ei[NE + idx]; }
    else          { r = c = idx - NE; }               // self loop
    int p = atomicAdd(&g_cur[c], 1);
    g_csr[p] = r;
}

// ---------------- lin1: h = relu(x @ W1 + b1) -> x_all[:,0,:] ----------------
__global__ void k_lin1(const float* __restrict__ x, const float* __restrict__ w,
                       const float* __restrict__ b) {
    int gw = (blockIdx.x * blockDim.x + threadIdx.x) >> 5;
    int lane = threadIdx.x & 31;
    int base = gw * 8;                 // NN % 8 == 0
    if (base >= NN) return;
    const float2* W2 = (const float2*)w;   // [256][32] float2
    float2 acc[8];
#pragma unroll
    for (int n = 0; n < 8; n++) acc[n] = make_float2(0.f, 0.f);
    for (int k0 = 0; k0 < 256; k0 += 32) {
        float xr[8];
#pragma unroll
        for (int n = 0; n < 8; n++) xr[n] = x[(base + n) * 256 + k0 + lane];
#pragma unroll
        for (int kk = 0; kk < 32; kk++) {
            float2 wv = W2[(k0 + kk) * 32 + lane];
#pragma unroll
            for (int n = 0; n < 8; n++) {
                float bv = __shfl_sync(0xffffffffu, xr[n], kk);
                acc[n].x += bv * wv.x;
                acc[n].y += bv * wv.y;
            }
        }
    }
    float2 bb = ((const float2*)b)[lane];
#pragma unroll
    for (int n = 0; n < 8; n++) {
        float2* o = (float2*)&g_xall[((size_t)(base + n) * 4 + 0) * 64];
        o[lane] = make_float2(fmaxf(acc[n].x + bb.x, 0.f), fmaxf(acc[n].y + bb.y, 0.f));
    }
}

// ---------------- QKV helpers ----------------
// gather this lane's group inputs x[g0*8 + i] from the warp-held x row
__device__ __forceinline__ void gather8(float x0, float x1, int g0, float (&xa)[8]) {
#pragma unroll
    for (int i = 0; i < 8; i++) {
        int idx = g0 * 8 + i;
        float a = __shfl_sync(0xffffffffu, x0, idx & 31);
        float bsh = __shfl_sync(0xffffffffu, x1, idx & 31);
        xa[i] = (idx < 32) ? a : bsh;
    }
}

// load [8][8][8] weights into padded smem (stride 33 float2 per group)
__device__ __forceinline__ void load_w_padded(const float* __restrict__ w, float2* sw) {
    for (int i = threadIdx.x; i < 256; i += blockDim.x) {
        int g = i >> 5, r = i & 31;
        sw[g * 33 + r] = ((const float2*)w)[i];
    }
}

// ---------------- qkv1: V only (layer-0 attention is identity) ----------------
__global__ void k_qkv1(const float* __restrict__ wv, const float* __restrict__ bv) {
    __shared__ float2 swv[264];
    __shared__ float sbv[64];
    load_w_padded(wv, swv);
    if (threadIdx.x < 64) sbv[threadIdx.x] = bv[threadIdx.x];
    __syncthreads();
    int n = (blockIdx.x * blockDim.x + threadIdx.x) >> 5;
    if (n >= NN) return;
    int lane = threadIdx.x & 31;
    int g0 = lane >> 2;
    int wbase = g0 * 33 + (lane & 3);
    const float* xr = &g_xall[(size_t)n * 256];
    float x0 = xr[lane], x1 = xr[lane + 32];
    float xa[8];
    gather8(x0, x1, g0, xa);
    float2 vv = ((const float2*)sbv)[lane];
#pragma unroll
    for (int i = 0; i < 8; i++) {
        float2 wvv = swv[wbase + i * 4];
        vv.x += xa[i] * wvv.x;  vv.y += xa[i] * wvv.y;
    }
    float dr = g_dis[n];
    g_V1[n * 32 + lane] = f2u(vv.x * dr, vv.y * dr);
}

// ---------------- qkv2: layers {0,1} K,V + Q(layer1), net-layer-1 weights ----------------
__global__ void k_qkv2(const float* __restrict__ wq, const float* __restrict__ bq,
                       const float* __restrict__ wk, const float* __restrict__ bk,
                       const float* __restrict__ wv, const float* __restrict__ bv) {
    __shared__ float2 swq[264], swk[264], swv[264];
    __shared__ float sbq[64], sbk[64], sbv[64];
    load_w_padded(wq, swq);
    load_w_padded(wk, swk);
    load_w_padded(wv, swv);
    if (threadIdx.x < 64) {
        sbq[threadIdx.x] = bq[threadIdx.x];
        sbk[threadIdx.x] = bk[threadIdx.x];
        sbv[threadIdx.x] = bv[threadIdx.x];
    }
    __syncthreads();
    int n = (blockIdx.x * blockDim.x + threadIdx.x) >> 5;
    if (n >= NN) return;
    int lane = threadIdx.x & 31;
    int g0 = lane >> 2;
    int wbase = g0 * 33 + (lane & 3);
    float dr = g_dis[n];
    const float* xr = &g_xall[(size_t)n * 256];

    uint4 pack;
    // layer 0
    {
        float x0 = xr[lane], x1 = xr[lane + 32];
        float xa[8];
        gather8(x0, x1, g0, xa);
        float2 kk = ((const float2*)sbk)[lane];
        float2 vv = ((const float2*)sbv)[lane];
#pragma unroll
        for (int i = 0; i < 8; i++) {
            float2 wkv = swk[wbase + i * 4];
            kk.x += xa[i] * wkv.x;  kk.y += xa[i] * wkv.y;
            float2 wvv = swv[wbase + i * 4];
            vv.x += xa[i] * wvv.x;  vv.y += xa[i] * wvv.y;
        }
        pack.x = f2u(kk.x, kk.y);
        pack.y = f2u(vv.x * dr, vv.y * dr);
    }
    // layer 1 (+Q)
    {
        float x0 = xr[64 + lane], x1 = xr[64 + lane + 32];
        float xa[8];
        gather8(x0, x1, g0, xa);
        float2 kk = ((const float2*)sbk)[lane];
        float2 vv = ((const float2*)sbv)[lane];
        float2 qq = ((const float2*)sbq)[lane];
#pragma unroll
        for (int i = 0; i < 8; i++) {
            float2 wkv = swk[wbase + i * 4];
            kk.x += xa[i] * wkv.x;  kk.y += xa[i] * wkv.y;
            float2 wvv = swv[wbase + i * 4];
            vv.x += xa[i] * wvv.x;  vv.y += xa[i] * wvv.y;
            float2 wqv = swq[wbase + i * 4];
            qq.x += xa[i] * wqv.x;  qq.y += xa[i] * wqv.y;
        }
        pack.z = f2u(kk.x, kk.y);
        pack.w = f2u(vv.x * dr, vv.y * dr);
        g_Q[n * 32 + lane] = make_float2(qq.x * SC, qq.y * SC);
    }
    g_KVab[n * 32 + lane] = pack;
}

// ---------------- qkv3: layers {0,1,2} K,V + Q(layer2), net-layer-2 weights ----------------
__global__ void k_qkv3(const float* __restrict__ wq, const float* __restrict__ bq,
                       const float* __restrict__ wk, const float* __restrict__ bk,
                       const float* __restrict__ wv, const float* __restrict__ bv) {
    __shared__ float2 swq[264], swk[264], swv[264];
    __shared__ float sbq[64], sbk[64], sbv[64];
    load_w_padded(wq, swq);
    load_w_padded(wk, swk);
    load_w_padded(wv, swv);
    if (threadIdx.x < 64) {
        sbq[threadIdx.x] = bq[threadIdx.x];
        sbk[threadIdx.x] = bk[threadIdx.x];
        sbv[threadIdx.x] = bv[threadIdx.x];
    }
    __syncthreads();
    int n = (blockIdx.x * blockDim.x + threadIdx.x) >> 5;
    if (n >= NN) return;
    int lane = threadIdx.x & 31;
    int g0 = lane >> 2;
    int wbase = g0 * 33 + (lane & 3);
    float dr = g_dis[n];
    const float* xr = &g_xall[(size_t)n * 256];

    unsigned kvu[6];
#pragma unroll
    for (int layer = 0; layer < 3; layer++) {
        float x0 = xr[layer * 64 + lane], x1 = xr[layer * 64 + lane + 32];
        float xa[8];
        gather8(x0, x1, g0, xa);
        float2 kk = ((const float2*)sbk)[lane];
        float2 vv = ((const float2*)sbv)[lane];
#pragma unroll
        for (int i = 0; i < 8; i++) {
            float2 wkv = swk[wbase + i * 4];
            kk.x += xa[i] * wkv.x;  kk.y += xa[i] * wkv.y;
            float2 wvv = swv[wbase + i * 4];
            vv.x += xa[i] * wvv.x;  vv.y += xa[i] * wvv.y;
        }
        kvu[layer * 2]     = f2u(kk.x, kk.y);
        kvu[layer * 2 + 1] = f2u(vv.x * dr, vv.y * dr);
        if (layer == 2) {
            float2 qq = ((const float2*)sbq)[lane];
#pragma unroll
            for (int i = 0; i < 8; i++) {
                float2 wqv = swq[wbase + i * 4];
                qq.x += xa[i] * wqv.x;  qq.y += xa[i] * wqv.y;
            }
            g_Q[n * 32 + lane] = make_float2(qq.x * SC, qq.y * SC);
        }
    }
    g_KVab[n * 32 + lane] = make_uint4(kvu[0], kvu[1], kvu[2], kvu[3]);
    g_KVc[n * 32 + lane]  = make_uint2(kvu[4], kvu[5]);
}

// ---------------- edge kernels ----------------
// layer 0: attention over single source layer == identity -> pure gather-sum
__global__ void k_edge1() {
    int c = (blockIdx.x * blockDim.x + threadIdx.x) >> 5;
    if (c >= NN) return;
    int lane = threadIdx.x & 31;
    float ax = 0.f, ay = 0.f;
    int j = g_off[c], end = g_off[c + 1];
    const unsigned* __restrict__ V1 = g_V1;
    for (; j + 4 <= end; j += 4) {
        int r0 = g_csr[j], r1 = g_csr[j + 1], r2 = g_csr[j + 2], r3 = g_csr[j + 3];
        unsigned u0 = V1[r0 * 32 + lane];
        unsigned u1 = V1[r1 * 32 + lane];
        unsigned u2 = V1[r2 * 32 + lane];
        unsigned u3 = V1[r3 * 32 + lane];
        float2 f0 = u2f(u0), f1 = u2f(u1), f2 = u2f(u2), f3 = u2f(u3);
        ax += (f0.x + f1.x) + (f2.x + f3.x);
        ay += (f0.y + f1.y) + (f2.y + f3.y);
    }
    for (; j < end; j++) {
        float2 f = u2f(V1[g_csr[j] * 32 + lane]);
        ax += f.x;  ay += f.y;
    }
    float dc = g_dis[c];
    float2* xo = (float2*)&g_xall[(size_t)c * 256 + 64];
    xo[lane] = make_float2(fmaxf(ax * dc, 0.f), fmaxf(ay * dc, 0.f));
}

__device__ __forceinline__ void acc2(uint4 d, float2 qv, float& ax, float& ay) {
    float2 k0 = u2f(d.x), v0 = u2f(d.y), k1 = u2f(d.z), v1 = u2f(d.w);
    float s0 = qv.x * k0.x + qv.y * k0.y;
    s0 += __shfl_xor_sync(0xffffffffu, s0, 1);
    s0 += __shfl_xor_sync(0xffffffffu, s0, 2);
    float s1 = qv.x * k1.x + qv.y * k1.y;
    s1 += __shfl_xor_sync(0xffffffffu, s1, 1);
    s1 += __shfl_xor_sync(0xffffffffu, s1, 2);
    float m = fmaxf(s0, s1);
    float e0 = __expf(s0 - m), e1 = __expf(s1 - m);
    float inv = __fdividef(1.0f, e0 + e1);
    ax += (e0 * v0.x + e1 * v1.x) * inv;
    ay += (e0 * v0.y + e1 * v1.y) * inv;
}

__global__ void k_edge2() {
    int c = (blockIdx.x * blockDim.x + threadIdx.x) >> 5;
    if (c >= NN) return;
    int lane = threadIdx.x & 31;
    float2 qv = g_Q[c * 32 + lane];
    float ax = 0.f, ay = 0.f;
    int j = g_off[c], end = g_off[c + 1];
    const uint4* __restrict__ KV = g_KVab;
    for (; j + 4 <= end; j += 4) {
        int r0 = g_csr[j], r1 = g_csr[j + 1], r2 = g_csr[j + 2], r3 = g_csr[j + 3];
        uint4 d0 = KV[r0 * 32 + lane];
        uint4 d1 = KV[r1 * 32 + lane];
        uint4 d2 = KV[r2 * 32 + lane];
        uint4 d3 = KV[r3 * 32 + lane];
        acc2(d0, qv, ax, ay);
        acc2(d1, qv, ax, ay);
        acc2(d2, qv, ax, ay);
        acc2(d3, qv, ax, ay);
    }
    for (; j < end; j++) {
        acc2(KV[g_csr[j] * 32 + lane], qv, ax, ay);
    }
    float dc = g_dis[c];
    float2* xo = (float2*)&g_xall[(size_t)c * 256 + 128];
    xo[lane] = make_float2(fmaxf(ax * dc, 0.f), fmaxf(ay * dc, 0.f));
}

__device__ __forceinline__ void acc3(uint4 d, uint2 e, float2 qv, float& ax, float& ay) {
    float2 k0 = u2f(d.x), v0 = u2f(d.y), k1 = u2f(d.z), v1 = u2f(d.w);
    float2 k2 = u2f(e.x), v2 = u2f(e.y);
    float s0 = qv.x * k0.x + qv.y * k0.y;
    s0 += __shfl_xor_sync(0xffffffffu, s0, 1);
    s0 += __shfl_xor_sync(0xffffffffu, s0, 2);
    float s1 = qv.x * k1.x + qv.y * k1.y;
    s1 += __shfl_xor_sync(0xffffffffu, s1, 1);
    s1 += __shfl_xor_sync(0xffffffffu, s1, 2);
    float s2 = qv.x * k2.x + qv.y * k2.y;
    s2 += __shfl_xor_sync(0xffffffffu, s2, 1);
    s2 += __shfl_xor_sync(0xffffffffu, s2, 2);
    float m = fmaxf(fmaxf(s0, s1), s2);
    float e0 = __expf(s0 - m), e1 = __expf(s1 - m), e2 = __expf(s2 - m);
    float inv = __fdividef(1.0f, e0 + e1 + e2);
    ax += (e0 * v0.x + e1 * v1.x + e2 * v2.x) * inv;
    ay += (e0 * v0.y + e1 * v1.y + e2 * v2.y) * inv;
}

__global__ void k_edge3() {
    int c = (blockIdx.x * blockDim.x + threadIdx.x) >> 5;
    if (c >= NN) return;
    int lane = threadIdx.x & 31;
    float2 qv = g_Q[c * 32 + lane];
    float ax = 0.f, ay = 0.f;
    int j = g_off[c], end = g_off[c + 1];
    const uint4* __restrict__ KVa = g_KVab;
    const uint2* __restrict__ KVc = g_KVc;
    for (; j + 4 <= end; j += 4) {
        int r0 = g_csr[j], r1 = g_csr[j + 1], r2 = g_csr[j + 2], r3 = g_csr[j + 3];
        uint4 d0 = KVa[r0 * 32 + lane];
        uint4 d1 = KVa[r1 * 32 + lane];
        uint4 d2 = KVa[r2 * 32 + lane];
        uint4 d3 = KVa[r3 * 32 + lane];
        uint2 e0 = KVc[r0 * 32 + lane];
        uint2 e1 = KVc[r1 * 32 + lane];
        uint2 e2 = KVc[r2 * 32 + lane];
        uint2 e3 = KVc[r3 * 32 + lane];
        acc3(d0, e0, qv, ax, ay);
        acc3(d1, e1, qv, ax, ay);
        acc3(d2, e2, qv, ax, ay);
        acc3(d3, e3, qv, ax, ay);
    }
    for (; j < end; j++) {
        int r = g_csr[j];
        acc3(KVa[r * 32 + lane], KVc[r * 32 + lane], qv, ax, ay);
    }
    float dc = g_dis[c];
    float2* xo = (float2*)&g_xall[(size_t)c * 256 + 192];
    xo[lane] = make_float2(fmaxf(ax * dc, 0.f), fmaxf(ay * dc, 0.f));
}

// ---------------- lin2 + log_softmax ----------------
__global__ void k_lin2(const float* __restrict__ w, const float* __restrict__ b,
                       float* __restrict__ out) {
    __shared__ float sw[2048];   // [64][32]
    __shared__ float sb[32];
    for (int i = threadIdx.x; i < 2048; i += blockDim.x) sw[i] = w[i];
    if (threadIdx.x < 32) sb[threadIdx.x] = b[threadIdx.x];
    __syncthreads();
    int n = (blockIdx.x * blockDim.x + threadIdx.x) >> 5;
    if (n >= NN) return;
    int lane = threadIdx.x & 31;   // lane = class
    float x0 = g_xall[(size_t)n * 256 + 192 + lane];
    float x1 = g_xall[(size_t)n * 256 + 192 + lane + 32];
    float acc = sb[lane];
#pragma unroll
    for (int k = 0; k < 32; k++) acc += __shfl_sync(0xffffffffu, x0, k) * sw[k * 32 + lane];
#pragma unroll
    for (int k = 0; k < 32; k++) acc += __shfl_sync(0xffffffffu, x1, k) * sw[(k + 32) * 32 + lane];
    float m = acc;
#pragma unroll
    for (int o = 16; o; o >>= 1) m = fmaxf(m, __shfl_xor_sync(0xffffffffu, m, o));
    float e = __expf(acc - m);
    float sum = e;
#pragma unroll
    for (int o = 16; o; o >>= 1) sum += __shfl_xor_sync(0xffffffffu, sum, o);
    out[(size_t)n * 32 + lane] = acc - m - logf(sum);
}

// ---------------- launch ----------------
extern "C" void kernel_launch(void* const* d_in, const int* in_sizes, int n_in,
                              void* d_out, int out_size) {
    const float* x  = (const float*)d_in[0];
    const int*   ei = (const int*)d_in[1];
    const float* w1 = (const float*)d_in[2];
    const float* b1 = (const float*)d_in[3];
    const float* wq = (const float*)d_in[4];
    const float* bq = (const float*)d_in[5];
    const float* wk = (const float*)d_in[6];
    const float* bk = (const float*)d_in[7];
    const float* wv = (const float*)d_in[8];
    const float* bv = (const float*)d_in[9];
    const float* w2 = (const float*)d_in[10];
    const float* b2 = (const float*)d_in[11];
    float* out = (float*)d_out;

    // CSR + norm
    k_init_deg<<<(NN + 255) / 256, 256>>>();
    k_hist<<<(NE + 255) / 256, 256>>>(ei);
    k_scan_block<<<SCAN_NB, 256>>>();
    k_scan_fix<<<SCAN_NB, 256>>>();
    k_scatter<<<(EE + 255) / 256, 256>>>(ei);

    // encoder
    k_lin1<<<((NN / 8) * 32 + 255) / 256, 256>>>(x, w1, b1);

    // layer 0 (attention identity -> V-only)
    k_qkv1<<<(NN * 32 + 255) / 256, 256>>>(wv, bv);
    k_edge1<<<(NN * 32 + 255) / 256, 256>>>();
    // layer 1
    k_qkv2<<<(NN * 32 + 255) / 256, 256>>>(wq + 512, bq + 64, wk + 512, bk + 64, wv + 512, bv + 64);
    k_edge2<<<(NN * 32 + 255) / 256, 256>>>();
    // layer 2
    k_qkv3<<<(NN * 32 + 255) / 256, 256>>>(wq + 1024, bq + 128, wk + 1024, bk + 128, wv + 1024, bv + 128);
    k_edge3<<<(NN * 32 + 255) / 256, 256>>>();

    // classifier
    k_lin2<<<(NN * 32 + 255) / 256, 256>>>(w2, b2, out);
}